// round 16
// baseline (speedup 1.0000x reference)
#include <cuda_runtime.h>
#include <cstdint>

#define DIAM   1024
#define NPIX   (DIAM * DIAM)
#define N_WL   31
#define NEL    (NPIX * N_WL)        // 32,505,856
#define VEC    16
#define NTH    (NEL / VEC)          // 2,031,616 = 7936 * 256 exactly
#define RADIUS 512

// Phase rotation: 2-step Cody-Waite reduction (fp32-exact vs reference phase)
// + hardware sincos on |r|<=pi/4 + quadrant fix via sign-bit XOR.
__device__ __forceinline__ void rot_sincos(float ph, float& s_out, float& c_out) {
    float j = rintf(__fmul_rn(ph, 0.63661977236758134f));
    float r = fmaf(j, -1.5707963705062866e+00f, ph);
    r       = fmaf(j,  4.3711390001862449e-08f, r);
    int qi  = (int)j;
    float sr, cr;
    __sincosf(r, &sr, &cr);
    bool odd = (qi & 1);
    float ss = odd ? cr : sr;
    float cc = odd ? sr : cr;
    s_out = __int_as_float(__float_as_int(ss) ^ ((qi << 30) & 0x80000000));
    c_out = __int_as_float(__float_as_int(cc) ^ (((qi + 1) << 30) & 0x80000000));
}

__global__ __launch_bounds__(256)
void doe_kernel(const float* __restrict__ hw,     // height_map_weight [512]
                const float* __restrict__ fr,     // field_real [NEL]
                const float* __restrict__ fi,     // field_imag [NEL]
                const float* __restrict__ wl,     // wavelength [31]
                const float* __restrict__ noise,  // [NPIX]
                const float* __restrict__ rad,    // radius_distance [NPIX]
                float* __restrict__ out)          // [2*NEL]
{
    __shared__ float s_t[N_WL];   // k * delta_n per wavelength
    if (threadIdx.x < N_WL) {
        float l  = wl[threadIdx.x];
        float k  = __fdiv_rn(6.283185307179586f, l);
        float dn = __fsub_rn(__fadd_rn(1.5f, __fdiv_rn(4e-15f, __fmul_rn(l, l))), 1.0f);
        s_t[threadIdx.x] = __fmul_rn(k, dn);
    }
    __syncthreads();

    int q = blockIdx.x * blockDim.x + threadIdx.x;   // exact grid: q < NTH
    int e = q * VEC;
    unsigned p  = (unsigned)e / 31u;
    int      w0 = e - (int)(p * 31u);
    unsigned pB = p + (w0 > (N_WL - VEC));           // 16-span straddles <= 1 boundary

    // Ground-truth radius from the input (quantizer boundaries must match
    // the reference bit-for-bit; never recompute).
    float rA = rad[p];
    float rB = rad[pB];
    bool inA = (rA <= (float)RADIUS);
    bool inB = (rB <= (float)RADIUS);

    float4* oR = (float4*)(out + e);
    float4* oI = (float4*)(out + NEL + e);

    if (!inA && !inB) {
        float4 z = make_float4(0.f, 0.f, 0.f, 0.f);
        __stcs(oR,     z); __stcs(oR + 1, z); __stcs(oR + 2, z); __stcs(oR + 3, z);
        __stcs(oI,     z); __stcs(oI + 1, z); __stcs(oI + 2, z); __stcs(oI + 3, z);
        return;
    }

    // Front-batch 8 streaming loads: MLP_p1 = 8 (deep latency hiding)
    const float4* fr4 = (const float4*)(fr + e);
    const float4* fi4 = (const float4*)(fi + e);
    float4 fr0 = __ldcs(fr4);     float4 fr1 = __ldcs(fr4 + 1);
    float4 fr2 = __ldcs(fr4 + 2); float4 fr3 = __ldcs(fr4 + 3);
    float4 fi0 = __ldcs(fi4);     float4 fi1 = __ldcs(fi4 + 1);
    float4 fi2 = __ldcs(fi4 + 2); float4 fi3 = __ldcs(fi4 + 3);
    float nzA = noise[p];
    float nzB = noise[pB];

    // q_base_height with exact fp32 rounding (constant-folded)
    const float lam0 = 7e-07f;
    float n0 = __fadd_rn(1.5f, __fdiv_rn(4e-15f, __fmul_rn(lam0, lam0)));
    float qh = __fdiv_rn(lam0, __fsub_rn(n0, 1.0f));

    float hA = 0.0f, hB = 0.0f;
    if (inA) {
        int idx = min(max((int)ceilf(rA) - 1, 0), 511);
        float w = fminf(fmaxf(hw[idx], -1.0f), 1.0f);
        float tv = __fsub_rn(0.002f, __fmul_rn(qh, __fmul_rn(__fadd_rn(w, 1.0f), 0.5f)));
        hA = __fadd_rn(tv, nzA);
    }
    if (inB) {
        int idx = min(max((int)ceilf(rB) - 1, 0), 511);
        float w = fminf(fmaxf(hw[idx], -1.0f), 1.0f);
        float tv = __fsub_rn(0.002f, __fmul_rn(qh, __fmul_rn(__fadd_rn(w, 1.0f), 0.5f)));
        hB = __fadd_rn(tv, nzB);
    }

    float fv[16] = {fr0.x, fr0.y, fr0.z, fr0.w, fr1.x, fr1.y, fr1.z, fr1.w,
                    fr2.x, fr2.y, fr2.z, fr2.w, fr3.x, fr3.y, fr3.z, fr3.w};
    float gv[16] = {fi0.x, fi0.y, fi0.z, fi0.w, fi1.x, fi1.y, fi1.z, fi1.w,
                    fi2.x, fi2.y, fi2.z, fi2.w, fi3.x, fi3.y, fi3.z, fi3.w};

    // Half 0: elements 0..7 (bounded live range -> regs stay under control)
    {
        float ov[8], wv[8];
        #pragma unroll
        for (int k = 0; k < 8; k++) {
            int  wli    = w0 + k;
            bool second = (wli >= N_WL);
            int  wlm    = second ? wli - N_WL : wli;
            float h     = second ? hB : hA;
            bool  in    = second ? inB : inA;
            float s, c;
            rot_sincos(__fmul_rn(s_t[wlm], h), s, c);
            float o_r = __fsub_rn(__fmul_rn(fv[k], c), __fmul_rn(gv[k], s));
            float o_i = __fadd_rn(__fmul_rn(fv[k], s), __fmul_rn(gv[k], c));
            ov[k] = in ? o_r : 0.0f;
            wv[k] = in ? o_i : 0.0f;
        }
        __stcs(oR,     make_float4(ov[0], ov[1], ov[2], ov[3]));
        __stcs(oR + 1, make_float4(ov[4], ov[5], ov[6], ov[7]));
        __stcs(oI,     make_float4(wv[0], wv[1], wv[2], wv[3]));
        __stcs(oI + 1, make_float4(wv[4], wv[5], wv[6], wv[7]));
    }
    // Half 1: elements 8..15
    {
        float ov[8], wv[8];
        #pragma unroll
        for (int k = 8; k < 16; k++) {
            int  wli    = w0 + k;
            bool second = (wli >= N_WL);
            int  wlm    = second ? wli - N_WL : wli;
            float h     = second ? hB : hA;
            bool  in    = second ? inB : inA;
            float s, c;
            rot_sincos(__fmul_rn(s_t[wlm], h), s, c);
            float o_r = __fsub_rn(__fmul_rn(fv[k], c), __fmul_rn(gv[k], s));
            float o_i = __fadd_rn(__fmul_rn(fv[k], s), __fmul_rn(gv[k], c));
            ov[k - 8] = in ? o_r : 0.0f;
            wv[k - 8] = in ? o_i : 0.0f;
        }
        __stcs(oR + 2, make_float4(ov[0], ov[1], ov[2], ov[3]));
        __stcs(oR + 3, make_float4(ov[4], ov[5], ov[6], ov[7]));
        __stcs(oI + 2, make_float4(wv[0], wv[1], wv[2], wv[3]));
        __stcs(oI + 3, make_float4(wv[4], wv[5], wv[6], wv[7]));
    }
}

extern "C" void kernel_launch(void* const* d_in, const int* in_sizes, int n_in,
                              void* d_out, int out_size) {
    const float* hw    = (const float*)d_in[0];  // height_map_weight
    const float* fr    = (const float*)d_in[1];  // field_real
    const float* fi    = (const float*)d_in[2];  // field_imag
    const float* wl    = (const float*)d_in[3];  // wavelength
    const float* noise = (const float*)d_in[4];  // noise
    const float* rad   = (const float*)d_in[5];  // radius_distance
    // d_in[6] aperture == (rad <= 512), recomputed from loaded rad (validated R3/R6/R9)

    doe_kernel<<<NTH / 256, 256>>>(hw, fr, fi, wl, noise, rad, (float*)d_out);
}